// round 9
// baseline (speedup 1.0000x reference)
#include <cuda_runtime.h>
#include <cstdint>

// Problem constants
#define B_  256
#define C_  64
#define T_  406
#define D_  10
#define TD  4060
#define KP  4608          // [0,4060)=m*wn*x | [4060,4466)=mask | rest 0
#define MBLK 32
#define ZTOT 36           // KP / 128
#define ZCH 128
#define LDS_ 132          // padded smem row stride (conflict-free frags)

// Output offsets (floats): output_seq, input_seq, loss, indices, label, mask, proto_count
#define O_OUT  0
#define O_IN   1039360
#define O_LOSS 2078720
#define O_IDX  2095104
#define O_LAB  2095360
#define O_MASK 2095616
#define O_PC   2199552

#define N_GEMM (8 * ZTOT)            // 288
#define N_BLOCKS (N_GEMM + B_)       // 544

// main-kernel smem pool (words): Ys 32*132 | Ps 64*132 | wn 128
#define POOL_WORDS (4224 + 8448 + 128)
#define SMEM_BYTES (POOL_WORDS * 4)

// Static scratch
__device__ __align__(16) float g_wn[4096];   // normalized softplus, tail zero
__device__ __align__(16) float g_P[C_ * KP]; // 1.18 MB  P' rows
__device__ float g_part[ZTOT * B_ * C_];     // split-K partials
__device__ float g_S1part[ZTOT * B_];
__device__ unsigned g_cnt[8];

__device__ __forceinline__ uint32_t f2tf(float f) {
    uint32_t u; asm("cvt.rna.tf32.f32 %0, %1;" : "=r"(u) : "f"(f)); return u;
}

// ---------------------------------------------------------------------------
// Kernel 1: prep. 65 blocks, each computes softplus inline (identical
// reduction order everywhere -> identical inv).
//   blocks 0-63: P' row c = [p | -0.5*inv*Q | 0]
//   block 64:    g_wn (normalized, 4096 w/ zero tail) + proto_count
// ---------------------------------------------------------------------------
__global__ void __launch_bounds__(256) prep_kernel(
    const int* __restrict__ label, const float* __restrict__ proto,
    const float* __restrict__ w, const float* __restrict__ pcin,
    float* __restrict__ out)
{
    __shared__ __align__(16) float s_sp[TD];
    __shared__ float s_red[8];
    __shared__ int s_cnt[C_];
    int bid = blockIdx.x, tid = threadIdx.x;

    // softplus + deterministic sum
    float lsum = 0.f;
    for (int k = tid; k < TD; k += 256) {
        float xv = w[k];
        float sp = fmaxf(xv, 0.f) + log1pf(expf(-fabsf(xv)));  // jax softplus
        s_sp[k] = sp;
        lsum += sp;
    }
    for (int o = 16; o; o >>= 1) lsum += __shfl_xor_sync(0xffffffffu, lsum, o);
    if ((tid & 31) == 0) s_red[tid >> 5] = lsum;
    __syncthreads();
    float tot = 0.f;
    #pragma unroll
    for (int i = 0; i < 8; i++) tot += s_red[i];
    float inv = 1.f / tot;

    if (bid < C_) {
        // ---- P' row for class c ----
        int c = bid;
        const float* pr = proto + (size_t)c * TD;
        float* Pr = g_P + (size_t)c * KP;
        const float4* s4 = (const float4*)pr;
        float4* d4 = (float4*)Pr;
        for (int i = tid; i < TD / 4; i += 256) d4[i] = s4[i];
        for (int t = tid; t < T_; t += 256) {
            float q = 0.f;
            #pragma unroll
            for (int d = 0; d < D_; d++) {
                float pv = pr[t * D_ + d];
                q = fmaf(s_sp[t * D_ + d] * pv, pv, q);
            }
            Pr[TD + t] = -0.5f * inv * q;
        }
        for (int k = TD + T_ + tid; k < KP; k += 256) Pr[k] = 0.f;
    } else {
        // ---- g_wn + proto_count ----
        for (int k = tid; k < 4096; k += 256)
            g_wn[k] = (k < TD) ? s_sp[k] * inv : 0.f;
        if (tid < C_) s_cnt[tid] = 0;
        __syncthreads();
        atomicAdd(&s_cnt[label[tid]], 1);     // 256 threads == B_
        __syncthreads();
        if (tid < C_) out[O_PC + tid] = pcin[tid] + (float)s_cnt[tid];
    }
}

// ---------------------------------------------------------------------------
// Kernel 2: main. bid<288: gemm block (m=bid&7, z=bid>>3); bid>=288: copy
// block for sample b = bid-288. Last-arrival gemm block per m writes loss.
// ---------------------------------------------------------------------------
__global__ void __launch_bounds__(256) main_kernel(
    const float* __restrict__ x, const int* __restrict__ label,
    const float* __restrict__ mask, const float* __restrict__ proto,
    float* __restrict__ out)
{
    extern __shared__ float s_pool[];
    __shared__ float s1_s[MBLK];
    __shared__ int s_last;

    int bid = blockIdx.x, tid = threadIdx.x;

    if (bid >= N_GEMM) {
        // ---------------- copy block ----------------
        int b = bid - N_GEMM;
        const float4* xs = (const float4*)(x + (size_t)b * TD);
        float4* oin = (float4*)(out + O_IN + (size_t)b * TD);
        for (int i = tid; i < TD / 4; i += 256) oin[i] = xs[i];
        for (int t = tid; t < T_; t += 256)
            out[O_MASK + (size_t)b * T_ + t] = mask[(size_t)b * T_ + t];
        int lab = label[b];
        const float4* ps = (const float4*)(proto + (size_t)lab * TD);
        float4* od = (float4*)(out + O_OUT + (size_t)b * TD);
        for (int i = tid; i < TD / 4; i += 256) od[i] = ps[i];
        if (tid == 0) {
            out[O_IDX + b] = (float)lab;      // K=1 -> indices == label
            out[O_LAB + b] = (float)lab;
        }
        return;
    }

    // ---------------- GEMM block ----------------
    int m = bid & 7, z = bid >> 3;
    int bm0 = m * MBLK;
    int k0 = z * ZCH;
    uint32_t (*Ys)[LDS_] = (uint32_t(*)[LDS_])s_pool;
    uint32_t (*Ps)[LDS_] = (uint32_t(*)[LDS_])(s_pool + MBLK * LDS_);
    float* s_wn = s_pool + MBLK * LDS_ + C_ * LDS_;

    int lane = tid & 31, wd = tid >> 5;

    if (tid < ZCH) {
        int k = k0 + tid;
        s_wn[tid] = (k < 4096) ? g_wn[k] : 0.f;
    }
    __syncthreads();

    // ---- Y staging: [m*wn*x | mask | 0], S1 partial ----
    int row = tid >> 3, cg = tid & 7;
    int gr = bm0 + row;
    const float* xrow = x + (size_t)gr * TD;
    const float* mrow = mask + (size_t)gr * T_;
    float s1 = 0.f;
    #pragma unroll
    for (int i = 0; i < 4; i++) {
        int kc = k0 + cg * 16 + i * 4;                  // kc % 4 == 0
        float y[4] = {0.f, 0.f, 0.f, 0.f};
        if (kc < TD) {                                  // TD % 4 == 0: whole float4
            float4 xv = *(const float4*)&xrow[kc];
            float xx[4] = { xv.x, xv.y, xv.z, xv.w };
            #pragma unroll
            for (int j = 0; j < 4; j++) {
                float mm = __ldg(&mrow[(kc + j) / D_]);
                float yv = mm * s_wn[kc - k0 + j] * xx[j];
                y[j] = yv;
                s1 = fmaf(yv, xx[j], s1);
            }
        } else {
            #pragma unroll
            for (int j = 0; j < 4; j++) {
                int k = kc + j;
                y[j] = (k < TD + T_) ? __ldg(&mrow[k - TD]) : 0.f;
            }
        }
        uint4 u = { f2tf(y[0]), f2tf(y[1]), f2tf(y[2]), f2tf(y[3]) };
        *(uint4*)&Ys[row][cg * 16 + i * 4] = u;
    }
    // S1 partial: reduce over the 8 col-groups of this row (deterministic)
    s1 += __shfl_xor_sync(0xffffffffu, s1, 1);
    s1 += __shfl_xor_sync(0xffffffffu, s1, 2);
    s1 += __shfl_xor_sync(0xffffffffu, s1, 4);
    if (cg == 0) g_S1part[z * B_ + gr] = s1;

    // ---- P staging from g_P (coalesced float4) ----
    #pragma unroll
    for (int uu = 0; uu < 2; uu++) {
        int u = tid + uu * 256;
        int pr = u >> 3, pc = u & 7;
        const float* prow = g_P + (size_t)pr * KP + k0;
        #pragma unroll
        for (int i = 0; i < 4; i++) {
            float4 v = *(const float4*)&prow[pc * 16 + i * 4];
            uint4 uv = { f2tf(v.x), f2tf(v.y), f2tf(v.z), f2tf(v.w) };
            *(uint4*)&Ps[pr][pc * 16 + i * 4] = uv;
        }
    }
    __syncthreads();

    // ---- tf32 MMA: 32x64 tile over 128 staged cols ----
    int wm = (wd & 1) * 16, wncol = (wd >> 1) * 16;
    int g = lane >> 2, t4 = lane & 3;
    float acc[2][4];
    #pragma unroll
    for (int nf = 0; nf < 2; nf++)
        #pragma unroll
        for (int i = 0; i < 4; i++) acc[nf][i] = 0.f;

    #pragma unroll
    for (int kk = 0; kk < ZCH; kk += 8) {
        uint32_t a0 = Ys[wm + g][kk + t4];
        uint32_t a1 = Ys[wm + g + 8][kk + t4];
        uint32_t a2 = Ys[wm + g][kk + t4 + 4];
        uint32_t a3 = Ys[wm + g + 8][kk + t4 + 4];
        #pragma unroll
        for (int nf = 0; nf < 2; nf++) {
            uint32_t b0 = Ps[wncol + nf * 8 + g][kk + t4];
            uint32_t b1 = Ps[wncol + nf * 8 + g][kk + t4 + 4];
            asm("mma.sync.aligned.m16n8k8.row.col.f32.tf32.tf32.f32 "
                "{%0,%1,%2,%3}, {%4,%5,%6,%7}, {%8,%9}, {%0,%1,%2,%3};"
                : "+f"(acc[nf][0]), "+f"(acc[nf][1]),
                  "+f"(acc[nf][2]), "+f"(acc[nf][3])
                : "r"(a0), "r"(a1), "r"(a2), "r"(a3), "r"(b0), "r"(b1));
        }
    }

    // partials
    float* part = g_part + (size_t)z * B_ * C_;
    int orow = bm0 + wm + g;
    #pragma unroll
    for (int nf = 0; nf < 2; nf++) {
        int col = wncol + nf * 8 + 2 * t4;
        *(float2*)&part[orow * C_ + col]       = make_float2(acc[nf][0], acc[nf][1]);
        *(float2*)&part[(orow + 8) * C_ + col] = make_float2(acc[nf][2], acc[nf][3]);
    }

    // last-arrival loss epilogue (atomicInc wraps -> replay-safe)
    __threadfence();
    __syncthreads();
    if (tid == 0) {
        unsigned old = atomicInc(&g_cnt[m], ZTOT - 1);
        s_last = (old == ZTOT - 1);
    }
    __syncthreads();
    if (s_last) {
        for (int r = tid; r < MBLK; r += 256) {
            float v = 0.f;
            #pragma unroll
            for (int zz = 0; zz < ZTOT; zz++)
                v += __ldcg(&g_S1part[zz * B_ + bm0 + r]);
            s1_s[r] = v;
        }
        __syncthreads();
        for (int o = tid; o < MBLK * C_; o += 256) {
            int b = bm0 + (o >> 6), c = o & 63;
            float s = 0.f;
            #pragma unroll
            for (int zz = 0; zz < ZTOT; zz++)
                s += __ldcg(&g_part[(size_t)zz * B_ * C_ + b * C_ + c]);
            out[O_LOSS + b * C_ + c] = s1_s[o >> 6] - 2.f * s;
        }
    }
}

// ---------------------------------------------------------------------------
extern "C" void kernel_launch(void* const* d_in, const int* in_sizes, int n_in,
                              void* d_out, int out_size) {
    const float* input_seq  = (const float*)d_in[0];
    const int*   label      = (const int*)  d_in[1];
    const float* mask       = (const float*)d_in[2];
    const float* prototypes = (const float*)d_in[3];
    const float* weights    = (const float*)d_in[4];
    const float* protocount = (const float*)d_in[5];
    float* out = (float*)d_out;

    prep_kernel<<<C_ + 1, 256>>>(label, prototypes, weights, protocount, out);
    cudaFuncSetAttribute(main_kernel,
                         cudaFuncAttributeMaxDynamicSharedMemorySize, SMEM_BYTES);
    main_kernel<<<N_BLOCKS, 256, SMEM_BYTES>>>(input_seq, label, mask,
                                               prototypes, out);
}

// round 10
// speedup vs baseline: 1.2121x; 1.2121x over previous
#include <cuda_runtime.h>
#include <cstdint>

// Problem constants
#define B_  256
#define C_  64
#define T_  406
#define D_  10
#define TD  4060          // T*D
#define KP  4608          // virtual K: [0,4060)=m*wn*x | [4060,4466)=mask | rest 0
#define ZSPLIT 36
#define ZCH 128           // KP / ZSPLIT
#define STG 64            // k-cols per smem stage
#define MBLK 32
#define LDS_ 68           // smem row stride (pad -> conflict-free frags)

// Output offsets (floats): output_seq, input_seq, loss, indices, label, mask, proto_count
#define O_OUT  0
#define O_IN   1039360
#define O_LOSS 2078720
#define O_IDX  2095104
#define O_LAB  2095360
#define O_MASK 2095616
#define O_PC   2199552

// Static scratch
__device__ __align__(16) float g_wn[4060];             // normalized softplus weights
__device__ __align__(16) float g_P[C_ * KP];           // 1.18 MB  (P' rows)
__device__ float g_part[ZSPLIT * B_ * C_];             // GEMM partials
__device__ float g_S1part[ZSPLIT * B_];                // S1 partials per z
__device__ unsigned g_cnt[8];                           // per M-block arrival counters

__device__ __forceinline__ uint32_t f2tf(float f) {
    uint32_t u;
    asm("cvt.rna.tf32.f32 %0, %1;" : "=r"(u) : "f"(f));
    return u;
}

// ---------------------------------------------------------------------------
// Kernel 1: prep (identical to R5 — proven at 22.6us total).
//   blocks [0,64):  softplus (redundant, identical order) -> P' row c
//   blocks [64,320): pure data movement: input/mask pass-through, prototype
//                    gather, indices/label
//   block 320:      softplus -> write normalized g_wn; proto_count
// ---------------------------------------------------------------------------
__global__ void __launch_bounds__(256) prep_kernel(
    const float* __restrict__ x, const int* __restrict__ label,
    const float* __restrict__ mask, const float* __restrict__ proto,
    const float* __restrict__ w, const float* __restrict__ pcin,
    float* __restrict__ out)
{
    __shared__ float s_sp[TD];
    __shared__ float s_red[8];
    __shared__ int s_cnt[C_];
    int bid = blockIdx.x, tid = threadIdx.x;

    if (bid < C_ || bid == C_ + B_) {
        float lsum = 0.f;
        for (int k = tid; k < TD; k += 256) {
            float xv = w[k];
            float sp = fmaxf(xv, 0.f) + log1pf(expf(-fabsf(xv)));  // jax softplus
            s_sp[k] = sp;
            lsum += sp;
        }
        for (int o = 16; o; o >>= 1) lsum += __shfl_xor_sync(0xffffffffu, lsum, o);
        if ((tid & 31) == 0) s_red[tid >> 5] = lsum;
        __syncthreads();
        float tot = 0.f;
        #pragma unroll
        for (int i = 0; i < 8; i++) tot += s_red[i];
        float inv = 1.f / tot;

        if (bid < C_) {
            // ---- P' row for class c = [p | -0.5*inv*Q | 0] ----
            int c = bid;
            const float* pr = proto + (size_t)c * TD;
            float* Pr = g_P + (size_t)c * KP;
            const float4* s4 = (const float4*)pr;
            float4* d4 = (float4*)Pr;
            for (int i = tid; i < TD / 4; i += 256) d4[i] = s4[i];
            for (int t = tid; t < T_; t += 256) {
                float q = 0.f;
                #pragma unroll
                for (int d = 0; d < D_; d++) {
                    float pv = pr[t * D_ + d];
                    q = fmaf(s_sp[t * D_ + d] * pv, pv, q);
                }
                Pr[TD + t] = -0.5f * inv * q;
            }
            for (int k = TD + T_ + tid; k < KP; k += 256) Pr[k] = 0.f;
        } else {
            // ---- g_wn + proto_count ----
            for (int k = tid; k < TD; k += 256) g_wn[k] = s_sp[k] * inv;
            if (tid < C_) s_cnt[tid] = 0;
            __syncthreads();
            atomicAdd(&s_cnt[label[tid]], 1);          // 256 threads == B_
            __syncthreads();
            if (tid < C_) out[O_PC + tid] = pcin[tid] + (float)s_cnt[tid];
        }
    } else {
        // ---- pure copies for sample b ----
        int b = bid - C_;
        const float4* xs = (const float4*)(x + (size_t)b * TD);
        float4* oin = (float4*)(out + O_IN + (size_t)b * TD);
        for (int i = tid; i < TD / 4; i += 256) oin[i] = xs[i];
        for (int t = tid; t < T_; t += 256)
            out[O_MASK + (size_t)b * T_ + t] = mask[(size_t)b * T_ + t];

        int lab = label[b];
        const float4* ps = (const float4*)(proto + (size_t)lab * TD);
        float4* od = (float4*)(out + O_OUT + (size_t)b * TD);
        for (int i = tid; i < TD / 4; i += 256) od[i] = ps[i];
        if (tid == 0) {
            out[O_IDX + b] = (float)lab;               // K=1 -> indices == label
            out[O_LAB + b] = (float)lab;
        }
    }
}

// ---------------------------------------------------------------------------
// Kernel 2: tf32 tensor-core split-K GEMM, Y built on the fly, software-
// pipelined staging, S1 computed in-staging, fused loss epilogue.
// grid = (8 m-blocks of 32 rows, 36 z). 256 threads = 8 warps (2m x 4n).
// Identical to R5 except ZSPLIT 18->36 (2 stages of 64 per block).
// ---------------------------------------------------------------------------
__global__ void __launch_bounds__(256) gemm_kernel(
    const float* __restrict__ x, const float* __restrict__ mask,
    float* __restrict__ out)
{
    __shared__ uint32_t Ys[MBLK][LDS_];   // tf32 bit patterns
    __shared__ uint32_t Ps[C_][LDS_];
    __shared__ int s_last;

    int tid = threadIdx.x, lane = tid & 31, w = tid >> 5;
    int bm0 = blockIdx.x * MBLK;
    int z = blockIdx.y, kz = z * ZCH;
    int wm = (w & 1) * 16, wn = (w >> 1) * 16;
    int g = lane >> 2, t4 = lane & 3;
    int srow = tid >> 4, sq = tid & 15;   // staging row (0..15) / quad (0..15)

    float acc[2][4];
    #pragma unroll
    for (int nf = 0; nf < 2; nf++)
        #pragma unroll
        for (int i = 0; i < 4; i++) acc[nf][i] = 0.f;
    float s1a[2] = {0.f, 0.f};

    // prefetch registers for one stage
    float4 xv[2], pv[4];
    float wnv[2][4], mv[2][4];
    int cur_k0 = 0;

    auto load_stage = [&](int st) {
        int k0 = kz + st * STG + sq * 4;
        cur_k0 = k0;
        #pragma unroll
        for (int i = 0; i < 2; i++) {
            int r = bm0 + srow + i * 16;
            if (k0 < TD) {
                xv[i] = *(const float4*)&x[(size_t)r * TD + k0];
                float4 wq = *(const float4*)&g_wn[k0];
                wnv[i][0] = wq.x; wnv[i][1] = wq.y;
                wnv[i][2] = wq.z; wnv[i][3] = wq.w;
                #pragma unroll
                for (int j = 0; j < 4; j++) {
                    int t = (k0 + j) / D_;
                    mv[i][j] = __ldg(&mask[(size_t)r * T_ + t]);
                }
            } else {
                #pragma unroll
                for (int j = 0; j < 4; j++) {
                    int k = k0 + j;
                    mv[i][j] = (k < TD + T_) ? __ldg(&mask[(size_t)r * T_ + (k - TD)])
                                             : 0.f;
                }
            }
        }
        #pragma unroll
        for (int i = 0; i < 4; i++)
            pv[i] = *(const float4*)&g_P[(size_t)(srow + i * 16) * KP + k0];
    };

    auto store_stage = [&]() {
        #pragma unroll
        for (int i = 0; i < 2; i++) {
            float y[4];
            if (cur_k0 < TD) {
                float xx[4] = { xv[i].x, xv[i].y, xv[i].z, xv[i].w };
                #pragma unroll
                for (int j = 0; j < 4; j++) {
                    y[j] = mv[i][j] * wnv[i][j] * xx[j];
                    s1a[i] = fmaf(y[j], xx[j], s1a[i]);
                }
            } else {
                #pragma unroll
                for (int j = 0; j < 4; j++) y[j] = mv[i][j];
            }
            uint4 u = { f2tf(y[0]), f2tf(y[1]), f2tf(y[2]), f2tf(y[3]) };
            *(uint4*)&Ys[srow + i * 16][sq * 4] = u;
        }
        #pragma unroll
        for (int i = 0; i < 4; i++) {
            uint4 u = { f2tf(pv[i].x), f2tf(pv[i].y), f2tf(pv[i].z), f2tf(pv[i].w) };
            *(uint4*)&Ps[srow + i * 16][sq * 4] = u;
        }
    };

    load_stage(0);
    #pragma unroll
    for (int st = 0; st < ZCH / STG; st++) {
        store_stage();
        __syncthreads();
        if (st < ZCH / STG - 1) load_stage(st + 1);   // overlaps with mma below
        #pragma unroll
        for (int kk = 0; kk < STG; kk += 8) {
            uint32_t a0 = Ys[wm + g][kk + t4];
            uint32_t a1 = Ys[wm + g + 8][kk + t4];
            uint32_t a2 = Ys[wm + g][kk + t4 + 4];
            uint32_t a3 = Ys[wm + g + 8][kk + t4 + 4];
            #pragma unroll
            for (int nf = 0; nf < 2; nf++) {
                uint32_t b0 = Ps[wn + nf * 8 + g][kk + t4];
                uint32_t b1 = Ps[wn + nf * 8 + g][kk + t4 + 4];
                asm("mma.sync.aligned.m16n8k8.row.col.f32.tf32.tf32.f32 "
                    "{%0,%1,%2,%3}, {%4,%5,%6,%7}, {%8,%9}, {%0,%1,%2,%3};"
                    : "+f"(acc[nf][0]), "+f"(acc[nf][1]),
                      "+f"(acc[nf][2]), "+f"(acc[nf][3])
                    : "r"(a0), "r"(a1), "r"(a2), "r"(a3), "r"(b0), "r"(b1));
            }
        }
        __syncthreads();
    }

    // GEMM partials
    float* part = g_part + (size_t)z * B_ * C_;
    int orow = bm0 + wm + g;
    #pragma unroll
    for (int nf = 0; nf < 2; nf++) {
        int col = wn + nf * 8 + 2 * t4;
        *(float2*)&part[orow * C_ + col]       = make_float2(acc[nf][0], acc[nf][1]);
        *(float2*)&part[(orow + 8) * C_ + col] = make_float2(acc[nf][2], acc[nf][3]);
    }

    // S1 partials: reduce over the 16 staging threads of each row (deterministic)
    #pragma unroll
    for (int i = 0; i < 2; i++) {
        float v = s1a[i];
        #pragma unroll
        for (int o = 8; o; o >>= 1) v += __shfl_xor_sync(0xffffffffu, v, o);
        if ((lane & 15) == 0) g_S1part[z * B_ + bm0 + srow + i * 16] = v;
    }

    // last-z-block-done loss epilogue (atomicInc wraps -> replay-safe)
    __threadfence();
    __syncthreads();
    if (tid == 0) {
        unsigned old = atomicInc(&g_cnt[blockIdx.x], ZSPLIT - 1);
        s_last = (old == ZSPLIT - 1);
    }
    __syncthreads();
    if (s_last) {
        for (int o = tid; o < MBLK * C_; o += 256) {
            int b = bm0 + (o >> 6), c = o & 63;
            float s = 0.f, s1 = 0.f;
            #pragma unroll
            for (int zz = 0; zz < ZSPLIT; zz++) {
                s  += __ldcg(&g_part[(size_t)zz * B_ * C_ + b * C_ + c]);
                s1 += __ldcg(&g_S1part[zz * B_ + b]);
            }
            out[O_LOSS + b * C_ + c] = s1 - 2.f * s;
        }
    }
}

// ---------------------------------------------------------------------------
extern "C" void kernel_launch(void* const* d_in, const int* in_sizes, int n_in,
                              void* d_out, int out_size) {
    const float* input_seq  = (const float*)d_in[0];
    const int*   label      = (const int*)  d_in[1];
    const float* mask       = (const float*)d_in[2];
    const float* prototypes = (const float*)d_in[3];
    const float* weights    = (const float*)d_in[4];
    const float* protocount = (const float*)d_in[5];
    float* out = (float*)d_out;

    prep_kernel<<<C_ + B_ + 1, 256>>>(input_seq, label, mask, prototypes,
                                      weights, protocount, out);
    gemm_kernel<<<dim3(8, ZSPLIT), 256>>>(input_seq, mask, out);
}

// round 11
// speedup vs baseline: 1.3617x; 1.1234x over previous
#include <cuda_runtime.h>
#include <cstdint>

// Problem constants
#define B_  256
#define C_  64
#define T_  406
#define D_  10
#define TD  4060          // T*D
#define KP  4608          // virtual K: [0,4060)=sp*m*x | [4060,4466)=mask | rest 0
#define ZSPLIT 18
#define ZCH 256           // KP / ZSPLIT
#define STG 64            // k-cols per smem stage
#define MBLK 32
#define LDS_ 68           // smem row stride (pad -> conflict-free frags)

// Output offsets (floats): output_seq, input_seq, loss, indices, label, mask, proto_count
#define O_OUT  0
#define O_IN   1039360
#define O_LOSS 2078720
#define O_IDX  2095104
#define O_LAB  2095360
#define O_MASK 2095616
#define O_PC   2199552

// Static scratch (all quantities UNNORMALIZED; inv applied in loss epilogue)
__device__ __align__(16) float g_P[C_ * KP];  // P' rows: [p | -0.5*Qu | 0]
__device__ float g_spsum[4];                   // softplus partial sums (per t-group)
__device__ float g_part[ZSPLIT * B_ * C_];     // GEMM partials
__device__ float g_S1part[ZSPLIT * B_];        // S1u partials per z
__device__ unsigned g_cnt[8];                   // per M-block arrival counters

__device__ __forceinline__ uint32_t f2tf(float f) {
    uint32_t u;
    asm("cvt.rna.tf32.f32 %0, %1;" : "=r"(u) : "f"(f));
    return u;
}
__device__ __forceinline__ float softplus_f(float x) {
    return fmaxf(x, 0.f) + log1pf(expf(-fabsf(x)));   // jax softplus
}

// ---------------------------------------------------------------------------
// Kernel 1: prep.
//   blocks [0,64):   P'Q block (cg=bid>>2 -> 4 c-rows, tg=bid&3 -> ~102 t):
//                    local softplus (1020 cols only), copy p-cols into g_P,
//                    compute -0.5*Qu mask-cols, tg3 zero-pads, cg0 writes spsum.
//   blocks [64,320): pure copies for sample b (pass-throughs, gather, idx/label)
//   block 320:       proto_count
// ---------------------------------------------------------------------------
__global__ void __launch_bounds__(256) prep_kernel(
    const float* __restrict__ x, const int* __restrict__ label,
    const float* __restrict__ mask, const float* __restrict__ proto,
    const float* __restrict__ w, const float* __restrict__ pcin,
    float* __restrict__ out)
{
    __shared__ float s_sp[1020];
    __shared__ float s_p[4][1020];
    __shared__ float s_red[8];
    __shared__ int s_cnt[C_];
    int bid = blockIdx.x, tid = threadIdx.x;

    if (bid < C_) {
        int cg = bid >> 2, tg = bid & 3;
        int c0 = cg * 4;
        int t0 = tg * 102;
        int t1 = (t0 + 102 < T_) ? t0 + 102 : T_;     // tg3: 306..406
        int nt = t1 - t0;
        int w0 = t0 * D_, nw = nt * D_;               // 1020 / 1000

        // local softplus
        for (int j = tid; j < nw; j += 256) s_sp[j] = softplus_f(w[w0 + j]);

        // copy p-cols into g_P + stage into smem (float4; nw % 4 == 0)
        {
            const float4* proto4 = (const float4*)proto;
            float4* gP4 = (float4*)g_P;
            int nq = nw >> 2, q0 = w0 >> 2;
            for (int idx = tid; idx < 4 * nq; idx += 256) {
                int rowl = idx / nq, q = idx - rowl * nq;
                float4 v = proto4[(size_t)(c0 + rowl) * (TD / 4) + q0 + q];
                *(float4*)&s_p[rowl][q * 4] = v;
                gP4[(size_t)(c0 + rowl) * (KP / 4) + q0 + q] = v;
            }
        }
        __syncthreads();

        // Qu mask-cols
        #pragma unroll
        for (int cl = 0; cl < 4; cl++) {
            for (int tt = tid; tt < nt; tt += 256) {
                float q = 0.f;
                #pragma unroll
                for (int d = 0; d < D_; d++) {
                    float pv = s_p[cl][tt * D_ + d];
                    q = fmaf(s_sp[tt * D_ + d] * pv, pv, q);
                }
                g_P[(size_t)(c0 + cl) * KP + TD + t0 + tt] = -0.5f * q;
            }
        }
        // zero tail cols [4466, 4608)
        if (tg == 3) {
            for (int k = TD + T_ + tid; k < KP; k += 256) {
                #pragma unroll
                for (int cl = 0; cl < 4; cl++)
                    g_P[(size_t)(c0 + cl) * KP + k] = 0.f;
            }
        }
        // spsum partial (single writer per tg, deterministic fixed order)
        if (cg == 0) {
            float s = 0.f;
            for (int j = tid; j < nw; j += 256) s += s_sp[j];
            for (int o = 16; o; o >>= 1) s += __shfl_xor_sync(0xffffffffu, s, o);
            if ((tid & 31) == 0) s_red[tid >> 5] = s;
            __syncthreads();
            if (tid == 0) {
                float v = 0.f;
                #pragma unroll
                for (int i = 0; i < 8; i++) v += s_red[i];
                g_spsum[tg] = v;
            }
        }
    } else if (bid < C_ + B_) {
        // ---- pure copies for sample b ----
        int b = bid - C_;
        const float4* xs = (const float4*)(x + (size_t)b * TD);
        float4* oin = (float4*)(out + O_IN + (size_t)b * TD);
        for (int i = tid; i < TD / 4; i += 256) oin[i] = xs[i];
        for (int t = tid; t < T_; t += 256)
            out[O_MASK + (size_t)b * T_ + t] = mask[(size_t)b * T_ + t];

        int lab = label[b];
        const float4* ps = (const float4*)(proto + (size_t)lab * TD);
        float4* od = (float4*)(out + O_OUT + (size_t)b * TD);
        for (int i = tid; i < TD / 4; i += 256) od[i] = ps[i];
        if (tid == 0) {
            out[O_IDX + b] = (float)lab;               // K=1 -> indices == label
            out[O_LAB + b] = (float)lab;
        }
    } else {
        // ---- proto_count ----
        if (tid < C_) s_cnt[tid] = 0;
        __syncthreads();
        atomicAdd(&s_cnt[label[tid]], 1);              // 256 threads == B_
        __syncthreads();
        if (tid < C_) out[O_PC + tid] = pcin[tid] + (float)s_cnt[tid];
    }
}

// ---------------------------------------------------------------------------
// Kernel 2: tf32 tensor-core split-K GEMM (R5 structure: 8m x 18z, 256 thr),
// Y built on the fly (UNNORMALIZED sp computed locally), mask via smem tile
// for x-chunks, pipelined staging, S1u in-staging, loss epilogue applies inv.
// ---------------------------------------------------------------------------
__global__ void __launch_bounds__(256) gemm_kernel(
    const float* __restrict__ x, const float* __restrict__ mask,
    const float* __restrict__ w, float* __restrict__ out)
{
    __shared__ uint32_t Ys[MBLK][LDS_];   // tf32 bit patterns
    __shared__ uint32_t Ps[C_][LDS_];
    __shared__ float s_sp[ZCH];           // local softplus chunk (unnormalized)
    __shared__ float s_mk[MBLK][28];      // mask tile for x-cols of this chunk
    __shared__ int s_last;

    int tid = threadIdx.x, lane = tid & 31, wd = tid >> 5;
    int bm0 = blockIdx.x * MBLK;
    int z = blockIdx.y, kz = z * ZCH;
    int wm = (wd & 1) * 16, wn = (wd >> 1) * 16;
    int g = lane >> 2, t4 = lane & 3;
    int srow = tid >> 4, sq = tid & 15;   // staging row (0..15) / quad (0..15)

    // local softplus chunk: 1 MUFU-pair per thread
    {
        int k = kz + tid;
        s_sp[tid] = (k < TD) ? softplus_f(w[k]) : 0.f;
    }
    // mask tile for x-cols: t range [kz/10 .. (kz+255)/10] (<= 26 values)
    int t0m = kz / D_;
    if (kz < TD) {
        int tcnt = ((kz + ZCH - 1 < TD ? kz + ZCH - 1 : TD - 1) / D_) - t0m + 1;
        for (int i = tid; i < MBLK * 28; i += 256) {
            int r = i >> 5;                            // wait: 28 stride
            ;
        }
        // (use explicit 28-wide indexing)
        for (int i = tid; i < MBLK * 28; i += 256) {
            int r = i / 28, tt = i - r * 28;
            float v = 0.f;
            if (tt < tcnt) v = mask[(size_t)(bm0 + r) * T_ + t0m + tt];
            s_mk[r][tt] = v;
        }
    }
    __syncthreads();

    float acc[2][4];
    #pragma unroll
    for (int nf = 0; nf < 2; nf++)
        #pragma unroll
        for (int i = 0; i < 4; i++) acc[nf][i] = 0.f;
    float s1a[2] = {0.f, 0.f};

    // prefetch registers for one stage
    float4 xv[2], pv[4];
    float mv[2][4];
    int cur_k0 = 0;

    auto load_stage = [&](int st) {
        int k0 = kz + st * STG + sq * 4;
        cur_k0 = k0;
        #pragma unroll
        for (int i = 0; i < 2; i++) {
            int r = bm0 + srow + i * 16;
            if (k0 < TD) {
                xv[i] = *(const float4*)&x[(size_t)r * TD + k0];
            } else {
                #pragma unroll
                for (int j = 0; j < 4; j++) {
                    int k = k0 + j;
                    mv[i][j] = (k < TD + T_) ? __ldg(&mask[(size_t)r * T_ + (k - TD)])
                                             : 0.f;
                }
            }
        }
        #pragma unroll
        for (int i = 0; i < 4; i++)
            pv[i] = *(const float4*)&g_P[(size_t)(srow + i * 16) * KP + k0];
    };

    auto store_stage = [&]() {
        #pragma unroll
        for (int i = 0; i < 2; i++) {
            float y[4];
            if (cur_k0 < TD) {
                float xx[4] = { xv[i].x, xv[i].y, xv[i].z, xv[i].w };
                #pragma unroll
                for (int j = 0; j < 4; j++) {
                    float mm = s_mk[srow + i * 16][(cur_k0 + j) / D_ - t0m];
                    float yv = mm * s_sp[cur_k0 - kz + j] * xx[j];
                    y[j] = yv;
                    s1a[i] = fmaf(yv, xx[j], s1a[i]);
                }
            } else {
                #pragma unroll
                for (int j = 0; j < 4; j++) y[j] = mv[i][j];
            }
            uint4 u = { f2tf(y[0]), f2tf(y[1]), f2tf(y[2]), f2tf(y[3]) };
            *(uint4*)&Ys[srow + i * 16][sq * 4] = u;
        }
        #pragma unroll
        for (int i = 0; i < 4; i++) {
            uint4 u = { f2tf(pv[i].x), f2tf(pv[i].y), f2tf(pv[i].z), f2tf(pv[i].w) };
            *(uint4*)&Ps[srow + i * 16][sq * 4] = u;
        }
    };

    load_stage(0);
    #pragma unroll
    for (int st = 0; st < ZCH / STG; st++) {
        store_stage();
        __syncthreads();
        if (st < ZCH / STG - 1) load_stage(st + 1);   // overlaps with mma below
        #pragma unroll
        for (int kk = 0; kk < STG; kk += 8) {
            uint32_t a0 = Ys[wm + g][kk + t4];
            uint32_t a1 = Ys[wm + g + 8][kk + t4];
            uint32_t a2 = Ys[wm + g][kk + t4 + 4];
            uint32_t a3 = Ys[wm + g + 8][kk + t4 + 4];
            #pragma unroll
            for (int nf = 0; nf < 2; nf++) {
                uint32_t b0 = Ps[wn + nf * 8 + g][kk + t4];
                uint32_t b1 = Ps[wn + nf * 8 + g][kk + t4 + 4];
                asm("mma.sync.aligned.m16n8k8.row.col.f32.tf32.tf32.f32 "
                    "{%0,%1,%2,%3}, {%4,%5,%6,%7}, {%8,%9}, {%0,%1,%2,%3};"
                    : "+f"(acc[nf][0]), "+f"(acc[nf][1]),
                      "+f"(acc[nf][2]), "+f"(acc[nf][3])
                    : "r"(a0), "r"(a1), "r"(a2), "r"(a3), "r"(b0), "r"(b1));
            }
        }
        __syncthreads();
    }

    // GEMM partials
    float* part = g_part + (size_t)z * B_ * C_;
    int orow = bm0 + wm + g;
    #pragma unroll
    for (int nf = 0; nf < 2; nf++) {
        int col = wn + nf * 8 + 2 * t4;
        *(float2*)&part[orow * C_ + col]       = make_float2(acc[nf][0], acc[nf][1]);
        *(float2*)&part[(orow + 8) * C_ + col] = make_float2(acc[nf][2], acc[nf][3]);
    }

    // S1u partials: reduce over the 16 staging threads of each row (deterministic)
    #pragma unroll
    for (int i = 0; i < 2; i++) {
        float v = s1a[i];
        #pragma unroll
        for (int o = 8; o; o >>= 1) v += __shfl_xor_sync(0xffffffffu, v, o);
        if ((lane & 15) == 0) g_S1part[z * B_ + bm0 + srow + i * 16] = v;
    }

    // last-z-block-done loss epilogue (atomicInc wraps -> replay-safe)
    __threadfence();
    __syncthreads();
    if (tid == 0) {
        unsigned old = atomicInc(&g_cnt[blockIdx.x], ZSPLIT - 1);
        s_last = (old == ZSPLIT - 1);
    }
    __syncthreads();
    if (s_last) {
        float inv = 1.f / (__ldg(&g_spsum[0]) + __ldg(&g_spsum[1]) +
                           __ldg(&g_spsum[2]) + __ldg(&g_spsum[3]));
        for (int o = tid; o < MBLK * C_; o += 256) {
            int b = bm0 + (o >> 6), c = o & 63;
            float s = 0.f, s1 = 0.f;
            #pragma unroll
            for (int zz = 0; zz < ZSPLIT; zz++) {
                s  += __ldcg(&g_part[(size_t)zz * B_ * C_ + b * C_ + c]);
                s1 += __ldcg(&g_S1part[zz * B_ + b]);
            }
            out[O_LOSS + b * C_ + c] = inv * (s1 - 2.f * s);
        }
    }
}

// ---------------------------------------------------------------------------
extern "C" void kernel_launch(void* const* d_in, const int* in_sizes, int n_in,
                              void* d_out, int out_size) {
    const float* input_seq  = (const float*)d_in[0];
    const int*   label      = (const int*)  d_in[1];
    const float* mask       = (const float*)d_in[2];
    const float* prototypes = (const float*)d_in[3];
    const float* weights    = (const float*)d_in[4];
    const float* protocount = (const float*)d_in[5];
    float* out = (float*)d_out;

    prep_kernel<<<C_ + B_ + 1, 256>>>(input_seq, label, mask, prototypes,
                                      weights, protocount, out);
    gemm_kernel<<<dim3(8, ZSPLIT), 256>>>(input_seq, mask, weights, out);
}

// round 12
// speedup vs baseline: 1.5071x; 1.1068x over previous
#include <cuda_runtime.h>
#include <cstdint>

// Problem constants
#define B_  256
#define C_  64
#define T_  406
#define D_  10
#define TD  4060          // T*D
#define KP  4608          // virtual K: [0,4060)=sp*m*x | [4060,4466)=mask | rest 0
#define ZSPLIT 18
#define ZCH 256           // KP / ZSPLIT
#define STG 64            // k-cols per smem stage
#define MBLK 32
#define LDS_ 68           // smem row stride (pad -> conflict-free frags)
#define NTHR 512

// Output offsets (floats): output_seq, input_seq, loss, indices, label, mask, proto_count
#define O_OUT  0
#define O_IN   1039360
#define O_LOSS 2078720
#define O_IDX  2095104
#define O_LAB  2095360
#define O_MASK 2095616
#define O_PC   2199552

// Static scratch (all quantities UNNORMALIZED; inv applied in loss epilogue)
__device__ __align__(16) float g_P[C_ * KP];  // P' rows: [p | -0.5*Qu | 0]
__device__ float g_spsum[4];                   // softplus partial sums (per t-group)
__device__ float g_part[ZSPLIT * B_ * C_];     // GEMM partials
__device__ float g_S1part[ZSPLIT * B_];        // S1u partials per z
__device__ unsigned g_cnt[8];                   // per M-block arrival counters

__device__ __forceinline__ uint32_t f2tf(float f) {
    uint32_t u;
    asm("cvt.rna.tf32.f32 %0, %1;" : "=r"(u) : "f"(f));
    return u;
}
__device__ __forceinline__ float softplus_f(float x) {
    return fmaxf(x, 0.f) + log1pf(expf(-fabsf(x)));   // jax softplus
}

// ---------------------------------------------------------------------------
// Kernel 1: prep (R11 verbatim — fast, passed).
//   blocks [0,64):   P'Q block (cg=bid>>2 -> 4 c-rows, tg=bid&3 -> ~102 t):
//                    local softplus, copy p-cols into g_P, -0.5*Qu mask-cols,
//                    tg3 zero-pads, cg0 writes spsum partial.
//   blocks [64,320): pure copies for sample b
//   block 320:       proto_count
// ---------------------------------------------------------------------------
__global__ void __launch_bounds__(256) prep_kernel(
    const float* __restrict__ x, const int* __restrict__ label,
    const float* __restrict__ mask, const float* __restrict__ proto,
    const float* __restrict__ w, const float* __restrict__ pcin,
    float* __restrict__ out)
{
    __shared__ float s_sp[1020];
    __shared__ float s_p[4][1020];
    __shared__ float s_red[8];
    __shared__ int s_cnt[C_];
    int bid = blockIdx.x, tid = threadIdx.x;

    if (bid < C_) {
        int cg = bid >> 2, tg = bid & 3;
        int c0 = cg * 4;
        int t0 = tg * 102;
        int t1 = (t0 + 102 < T_) ? t0 + 102 : T_;
        int nt = t1 - t0;
        int w0 = t0 * D_, nw = nt * D_;

        for (int j = tid; j < nw; j += 256) s_sp[j] = softplus_f(w[w0 + j]);

        {
            const float4* proto4 = (const float4*)proto;
            float4* gP4 = (float4*)g_P;
            int nq = nw >> 2, q0 = w0 >> 2;
            for (int idx = tid; idx < 4 * nq; idx += 256) {
                int rowl = idx / nq, q = idx - rowl * nq;
                float4 v = proto4[(size_t)(c0 + rowl) * (TD / 4) + q0 + q];
                *(float4*)&s_p[rowl][q * 4] = v;
                gP4[(size_t)(c0 + rowl) * (KP / 4) + q0 + q] = v;
            }
        }
        __syncthreads();

        #pragma unroll
        for (int cl = 0; cl < 4; cl++) {
            for (int tt = tid; tt < nt; tt += 256) {
                float q = 0.f;
                #pragma unroll
                for (int d = 0; d < D_; d++) {
                    float pv = s_p[cl][tt * D_ + d];
                    q = fmaf(s_sp[tt * D_ + d] * pv, pv, q);
                }
                g_P[(size_t)(c0 + cl) * KP + TD + t0 + tt] = -0.5f * q;
            }
        }
        if (tg == 3) {
            for (int k = TD + T_ + tid; k < KP; k += 256) {
                #pragma unroll
                for (int cl = 0; cl < 4; cl++)
                    g_P[(size_t)(c0 + cl) * KP + k] = 0.f;
            }
        }
        if (cg == 0) {
            float s = 0.f;
            for (int j = tid; j < nw; j += 256) s += s_sp[j];
            for (int o = 16; o; o >>= 1) s += __shfl_xor_sync(0xffffffffu, s, o);
            if ((tid & 31) == 0) s_red[tid >> 5] = s;
            __syncthreads();
            if (tid == 0) {
                float v = 0.f;
                #pragma unroll
                for (int i = 0; i < 8; i++) v += s_red[i];
                g_spsum[tg] = v;
            }
        }
    } else if (bid < C_ + B_) {
        int b = bid - C_;
        const float4* xs = (const float4*)(x + (size_t)b * TD);
        float4* oin = (float4*)(out + O_IN + (size_t)b * TD);
        for (int i = tid; i < TD / 4; i += 256) oin[i] = xs[i];
        for (int t = tid; t < T_; t += 256)
            out[O_MASK + (size_t)b * T_ + t] = mask[(size_t)b * T_ + t];

        int lab = label[b];
        const float4* ps = (const float4*)(proto + (size_t)lab * TD);
        float4* od = (float4*)(out + O_OUT + (size_t)b * TD);
        for (int i = tid; i < TD / 4; i += 256) od[i] = ps[i];
        if (tid == 0) {
            out[O_IDX + b] = (float)lab;               // K=1 -> indices == label
            out[O_LAB + b] = (float)lab;
        }
    } else {
        if (tid < C_) s_cnt[tid] = 0;
        __syncthreads();
        atomicAdd(&s_cnt[label[tid]], 1);              // 256 threads == B_
        __syncthreads();
        if (tid < C_) out[O_PC + tid] = pcin[tid] + (float)s_cnt[tid];
    }
}

// ---------------------------------------------------------------------------
// Kernel 2: tf32 split-K GEMM, 512 threads / 16 warps (2m x 8n grid, warp
// tile 16x8, one C-frag). grid = (8 m-blocks, 18 z). Y built on the fly
// (unnormalized sp local), pipelined staging, S1u in-staging, loss epilogue
// applies inv.
// ---------------------------------------------------------------------------
__global__ void __launch_bounds__(NTHR) gemm_kernel(
    const float* __restrict__ x, const float* __restrict__ mask,
    const float* __restrict__ w, float* __restrict__ out)
{
    __shared__ uint32_t Ys[MBLK][LDS_];   // tf32 bit patterns
    __shared__ uint32_t Ps[C_][LDS_];
    __shared__ float s_sp[ZCH];           // local softplus chunk (unnormalized)
    __shared__ int s_last;

    int tid = threadIdx.x, lane = tid & 31, wd = tid >> 5;
    int bm0 = blockIdx.x * MBLK;
    int z = blockIdx.y, kz = z * ZCH;
    int wm = (wd & 1) * 16, wn = (wd >> 1) * 8;   // 2m x 8n warp grid
    int g = lane >> 2, t4 = lane & 3;
    int srow = tid >> 4, sq = tid & 15;           // staging row (0..31) / quad

    // local softplus chunk (256 values, threads 0..255)
    if (tid < ZCH) {
        int k = kz + tid;
        s_sp[tid] = (k < TD) ? softplus_f(w[k]) : 0.f;
    }
    __syncthreads();

    float acc[4] = {0.f, 0.f, 0.f, 0.f};
    float s1a = 0.f;

    // prefetch registers for one stage (per thread: 1 Y float4, 2 P float4)
    float4 xv, pv[2];
    float mv[4];
    int cur_k0 = 0;

    auto load_stage = [&](int st) {
        int k0 = kz + st * STG + sq * 4;
        cur_k0 = k0;
        int r = bm0 + srow;
        if (k0 < TD) {
            xv = *(const float4*)&x[(size_t)r * TD + k0];
            #pragma unroll
            for (int j = 0; j < 4; j++)
                mv[j] = __ldg(&mask[(size_t)r * T_ + (k0 + j) / D_]);
        } else {
            #pragma unroll
            for (int j = 0; j < 4; j++) {
                int k = k0 + j;
                mv[j] = (k < TD + T_) ? __ldg(&mask[(size_t)r * T_ + (k - TD)])
                                      : 0.f;
            }
        }
        #pragma unroll
        for (int i = 0; i < 2; i++)
            pv[i] = *(const float4*)&g_P[(size_t)(srow + i * 32) * KP + k0];
    };

    auto store_stage = [&]() {
        float y[4];
        if (cur_k0 < TD) {
            float xx[4] = { xv.x, xv.y, xv.z, xv.w };
            #pragma unroll
            for (int j = 0; j < 4; j++) {
                float yv = mv[j] * s_sp[cur_k0 - kz + j] * xx[j];
                y[j] = yv;
                s1a = fmaf(yv, xx[j], s1a);
            }
        } else {
            #pragma unroll
            for (int j = 0; j < 4; j++) y[j] = mv[j];
        }
        uint4 u = { f2tf(y[0]), f2tf(y[1]), f2tf(y[2]), f2tf(y[3]) };
        *(uint4*)&Ys[srow][sq * 4] = u;
        #pragma unroll
        for (int i = 0; i < 2; i++) {
            uint4 up = { f2tf(pv[i].x), f2tf(pv[i].y), f2tf(pv[i].z), f2tf(pv[i].w) };
            *(uint4*)&Ps[srow + i * 32][sq * 4] = up;
        }
    };

    load_stage(0);
    #pragma unroll
    for (int st = 0; st < ZCH / STG; st++) {
        store_stage();
        __syncthreads();
        if (st < ZCH / STG - 1) load_stage(st + 1);   // overlaps with mma below
        #pragma unroll
        for (int kk = 0; kk < STG; kk += 8) {
            uint32_t a0 = Ys[wm + g][kk + t4];
            uint32_t a1 = Ys[wm + g + 8][kk + t4];
            uint32_t a2 = Ys[wm + g][kk + t4 + 4];
            uint32_t a3 = Ys[wm + g + 8][kk + t4 + 4];
            uint32_t b0 = Ps[wn + g][kk + t4];
            uint32_t b1 = Ps[wn + g][kk + t4 + 4];
            asm("mma.sync.aligned.m16n8k8.row.col.f32.tf32.tf32.f32 "
                "{%0,%1,%2,%3}, {%4,%5,%6,%7}, {%8,%9}, {%0,%1,%2,%3};"
                : "+f"(acc[0]), "+f"(acc[1]), "+f"(acc[2]), "+f"(acc[3])
                : "r"(a0), "r"(a1), "r"(a2), "r"(a3), "r"(b0), "r"(b1));
        }
        __syncthreads();
    }

    // GEMM partials
    float* part = g_part + (size_t)z * B_ * C_;
    int orow = bm0 + wm + g;
    int col = wn + 2 * t4;
    *(float2*)&part[orow * C_ + col]       = make_float2(acc[0], acc[1]);
    *(float2*)&part[(orow + 8) * C_ + col] = make_float2(acc[2], acc[3]);

    // S1u partials: reduce over the 16 staging threads of each row
    {
        float v = s1a;
        v += __shfl_xor_sync(0xffffffffu, v, 1);
        v += __shfl_xor_sync(0xffffffffu, v, 2);
        v += __shfl_xor_sync(0xffffffffu, v, 4);
        v += __shfl_xor_sync(0xffffffffu, v, 8);
        if ((lane & 15) == 0) g_S1part[z * B_ + bm0 + srow] = v;
    }

    // last-z-block-done loss epilogue (atomicInc wraps -> replay-safe)
    __threadfence();
    __syncthreads();
    if (tid == 0) {
        unsigned old = atomicInc(&g_cnt[blockIdx.x], ZSPLIT - 1);
        s_last = (old == ZSPLIT - 1);
    }
    __syncthreads();
    if (s_last) {
        float inv = 1.f / (__ldg(&g_spsum[0]) + __ldg(&g_spsum[1]) +
                           __ldg(&g_spsum[2]) + __ldg(&g_spsum[3]));
        for (int o = tid; o < MBLK * C_; o += NTHR) {
            int b = bm0 + (o >> 6), c = o & 63;
            float s = 0.f, s1 = 0.f;
            #pragma unroll
            for (int zz = 0; zz < ZSPLIT; zz++) {
                s  += __ldcg(&g_part[(size_t)zz * B_ * C_ + b * C_ + c]);
                s1 += __ldcg(&g_S1part[zz * B_ + b]);
            }
            out[O_LOSS + b * C_ + c] = inv * (s1 - 2.f * s);
        }
    }
}

// ---------------------------------------------------------------------------
extern "C" void kernel_launch(void* const* d_in, const int* in_sizes, int n_in,
                              void* d_out, int out_size) {
    const float* input_seq  = (const float*)d_in[0];
    const int*   label      = (const int*)  d_in[1];
    const float* mask       = (const float*)d_in[2];
    const float* prototypes = (const float*)d_in[3];
    const float* weights    = (const float*)d_in[4];
    const float* protocount = (const float*)d_in[5];
    float* out = (float*)d_out;

    prep_kernel<<<C_ + B_ + 1, 256>>>(input_seq, label, mask, prototypes,
                                      weights, protocount, out);
    gemm_kernel<<<dim3(8, ZSPLIT), NTHR>>>(input_seq, mask, weights, out);
}

// round 13
// speedup vs baseline: 1.5686x; 1.0408x over previous
#include <cuda_runtime.h>
#include <cstdint>

// Problem constants
#define B_  256
#define C_  64
#define T_  406
#define D_  10
#define TD  4060          // T*D
#define KP  4608          // virtual K: [0,4060)=sp*m*x | [4060,4466)=mask | rest 0
#define ZSPLIT 18
#define ZCH 256           // KP / ZSPLIT
#define STG 128           // k-cols per smem stage (2 stages per chunk)
#define MBLK 32
#define LDS_ 132          // smem row stride (pad -> conflict-free frags)
#define NTHR 1024

// Output offsets (floats): output_seq, input_seq, loss, indices, label, mask, proto_count
#define O_OUT  0
#define O_IN   1039360
#define O_LOSS 2078720
#define O_IDX  2095104
#define O_LAB  2095360
#define O_MASK 2095616
#define O_PC   2199552

// gemm smem pool (words): Ys 32*132=4224 | Ps 64*132=8448 | s_sp 256
#define POOL_WORDS (4224 + 8448 + 256)
#define GEMM_SMEM (POOL_WORDS * 4)

// Static scratch (all quantities UNNORMALIZED; inv applied in loss epilogue)
__device__ __align__(16) float g_P[C_ * KP];   // P' rows: [p | -0.5*Qu | 0]
__device__ float g_spsum[4];                    // softplus partial sums
__device__ float g_part[2 * ZSPLIT * B_ * C_];  // partials (slot 2z+wg)
__device__ float g_S1part[ZSPLIT * B_];         // S1u partials per z
__device__ unsigned g_cnt[8];                    // per M-block arrival counters

__device__ __forceinline__ uint32_t f2tf(float f) {
    uint32_t u;
    asm("cvt.rna.tf32.f32 %0, %1;" : "=r"(u) : "f"(f));
    return u;
}
__device__ __forceinline__ float softplus_f(float x) {
    return fmaxf(x, 0.f) + log1pf(expf(-fabsf(x)));   // jax softplus
}

// ---------------------------------------------------------------------------
// Kernel 1: prep (R11/R12 verbatim — passed).
// ---------------------------------------------------------------------------
__global__ void __launch_bounds__(256) prep_kernel(
    const float* __restrict__ x, const int* __restrict__ label,
    const float* __restrict__ mask, const float* __restrict__ proto,
    const float* __restrict__ w, const float* __restrict__ pcin,
    float* __restrict__ out)
{
    __shared__ float s_sp[1020];
    __shared__ float s_p[4][1020];
    __shared__ float s_red[8];
    __shared__ int s_cnt[C_];
    int bid = blockIdx.x, tid = threadIdx.x;

    if (bid < C_) {
        int cg = bid >> 2, tg = bid & 3;
        int c0 = cg * 4;
        int t0 = tg * 102;
        int t1 = (t0 + 102 < T_) ? t0 + 102 : T_;
        int nt = t1 - t0;
        int w0 = t0 * D_, nw = nt * D_;

        for (int j = tid; j < nw; j += 256) s_sp[j] = softplus_f(w[w0 + j]);

        {
            const float4* proto4 = (const float4*)proto;
            float4* gP4 = (float4*)g_P;
            int nq = nw >> 2, q0 = w0 >> 2;
            for (int idx = tid; idx < 4 * nq; idx += 256) {
                int rowl = idx / nq, q = idx - rowl * nq;
                float4 v = proto4[(size_t)(c0 + rowl) * (TD / 4) + q0 + q];
                *(float4*)&s_p[rowl][q * 4] = v;
                gP4[(size_t)(c0 + rowl) * (KP / 4) + q0 + q] = v;
            }
        }
        __syncthreads();

        #pragma unroll
        for (int cl = 0; cl < 4; cl++) {
            for (int tt = tid; tt < nt; tt += 256) {
                float q = 0.f;
                #pragma unroll
                for (int d = 0; d < D_; d++) {
                    float pv = s_p[cl][tt * D_ + d];
                    q = fmaf(s_sp[tt * D_ + d] * pv, pv, q);
                }
                g_P[(size_t)(c0 + cl) * KP + TD + t0 + tt] = -0.5f * q;
            }
        }
        if (tg == 3) {
            for (int k = TD + T_ + tid; k < KP; k += 256) {
                #pragma unroll
                for (int cl = 0; cl < 4; cl++)
                    g_P[(size_t)(c0 + cl) * KP + k] = 0.f;
            }
        }
        if (cg == 0) {
            float s = 0.f;
            for (int j = tid; j < nw; j += 256) s += s_sp[j];
            for (int o = 16; o; o >>= 1) s += __shfl_xor_sync(0xffffffffu, s, o);
            if ((tid & 31) == 0) s_red[tid >> 5] = s;
            __syncthreads();
            if (tid == 0) {
                float v = 0.f;
                #pragma unroll
                for (int i = 0; i < 8; i++) v += s_red[i];
                g_spsum[tg] = v;
            }
        }
    } else if (bid < C_ + B_) {
        int b = bid - C_;
        const float4* xs = (const float4*)(x + (size_t)b * TD);
        float4* oin = (float4*)(out + O_IN + (size_t)b * TD);
        for (int i = tid; i < TD / 4; i += 256) oin[i] = xs[i];
        for (int t = tid; t < T_; t += 256)
            out[O_MASK + (size_t)b * T_ + t] = mask[(size_t)b * T_ + t];

        int lab = label[b];
        const float4* ps = (const float4*)(proto + (size_t)lab * TD);
        float4* od = (float4*)(out + O_OUT + (size_t)b * TD);
        for (int i = tid; i < TD / 4; i += 256) od[i] = ps[i];
        if (tid == 0) {
            out[O_IDX + b] = (float)lab;               // K=1 -> indices == label
            out[O_LAB + b] = (float)lab;
        }
    } else {
        if (tid < C_) s_cnt[tid] = 0;
        __syncthreads();
        atomicAdd(&s_cnt[label[tid]], 1);              // 256 threads == B_
        __syncthreads();
        if (tid < C_) out[O_PC + tid] = pcin[tid] + (float)s_cnt[tid];
    }
}

// ---------------------------------------------------------------------------
// Kernel 2: tf32 split-K GEMM, 1024 threads / 32 warps.
// grid = (8 m-blocks, 18 z). Stage = 128 cols (2 stages/chunk).
// Warp-group wg = wd>>4 handles kk half [wg*64, wg*64+64) of each stage;
// within a group: 2m x 8n warp grid, warp tile 16x8.
// Warp wd stages exactly row wd (lane quads cover 128 cols).
// wg partials go to slot 2z+wg (fixed-order sum in epilogue -> deterministic).
// ---------------------------------------------------------------------------
__global__ void __launch_bounds__(NTHR) gemm_kernel(
    const float* __restrict__ x, const float* __restrict__ mask,
    const float* __restrict__ w, float* __restrict__ out)
{
    extern __shared__ float s_pool[];
    uint32_t (*Ys)[LDS_] = (uint32_t(*)[LDS_])s_pool;
    uint32_t (*Ps)[LDS_] = (uint32_t(*)[LDS_])(s_pool + MBLK * LDS_);
    float* s_sp = s_pool + MBLK * LDS_ + C_ * LDS_;
    __shared__ int s_last;

    int tid = threadIdx.x, lane = tid & 31, wd = tid >> 5;
    int bm0 = blockIdx.x * MBLK;
    int z = blockIdx.y, kz = z * ZCH;
    int wg = wd >> 4, wi = wd & 15;
    int wm = (wi & 1) * 16, wn = (wi >> 1) * 8;    // 2m x 8n per warp-group
    int g = lane >> 2, t4 = lane & 3;
    int srow = wd, sq = lane;                      // staging: warp wd = row wd

    // local softplus chunk (256 values)
    if (tid < ZCH) {
        int k = kz + tid;
        s_sp[tid] = (k < TD) ? softplus_f(w[k]) : 0.f;
    }

    float acc[4] = {0.f, 0.f, 0.f, 0.f};
    float s1a = 0.f;

    // prefetch registers for one stage (per thread: 1 Y float4, 2 P float4)
    float4 xv, pv[2];
    float mv[4];
    int cur_k0 = 0;

    auto load_stage = [&](int st) {
        int k0 = kz + st * STG + sq * 4;
        cur_k0 = k0;
        int r = bm0 + srow;
        if (k0 < TD) {
            xv = *(const float4*)&x[(size_t)r * TD + k0];
            #pragma unroll
            for (int j = 0; j < 4; j++)
                mv[j] = __ldg(&mask[(size_t)r * T_ + (k0 + j) / D_]);
        } else {
            #pragma unroll
            for (int j = 0; j < 4; j++) {
                int k = k0 + j;
                mv[j] = (k < TD + T_) ? __ldg(&mask[(size_t)r * T_ + (k - TD)])
                                      : 0.f;
            }
        }
        // P: 64 rows x 32 quads = 2048 float4, 2 per thread
        #pragma unroll
        for (int i = 0; i < 2; i++) {
            int u = tid + i * NTHR;                // 0..2047
            int pr = u >> 5, pq = u & 31;
            pv[i] = *(const float4*)&g_P[(size_t)pr * KP + kz + st * STG + pq * 4];
        }
    };

    auto store_stage = [&]() {
        float y[4];
        if (cur_k0 < TD) {
            float xx[4] = { xv.x, xv.y, xv.z, xv.w };
            #pragma unroll
            for (int j = 0; j < 4; j++) {
                float yv = mv[j] * s_sp[cur_k0 - kz + j] * xx[j];
                y[j] = yv;
                s1a = fmaf(yv, xx[j], s1a);
            }
        } else {
            #pragma unroll
            for (int j = 0; j < 4; j++) y[j] = mv[j];
        }
        uint4 u = { f2tf(y[0]), f2tf(y[1]), f2tf(y[2]), f2tf(y[3]) };
        *(uint4*)&Ys[srow][sq * 4] = u;
        #pragma unroll
        for (int i = 0; i < 2; i++) {
            int uu = tid + i * NTHR;
            int pr = uu >> 5, pq = uu & 31;
            uint4 up = { f2tf(pv[i].x), f2tf(pv[i].y), f2tf(pv[i].z), f2tf(pv[i].w) };
            *(uint4*)&Ps[pr][pq * 4] = up;
        }
    };

    load_stage(0);
    #pragma unroll
    for (int st = 0; st < ZCH / STG; st++) {
        store_stage();
        __syncthreads();
        if (st < ZCH / STG - 1) load_stage(st + 1);   // overlaps with mma below
        int kbase = wg * 64;
        #pragma unroll
        for (int kk = 0; kk < 64; kk += 8) {
            int kc = kbase + kk;
            uint32_t a0 = Ys[wm + g][kc + t4];
            uint32_t a1 = Ys[wm + g + 8][kc + t4];
            uint32_t a2 = Ys[wm + g][kc + t4 + 4];
            uint32_t a3 = Ys[wm + g + 8][kc + t4 + 4];
            uint32_t b0 = Ps[wn + g][kc + t4];
            uint32_t b1 = Ps[wn + g][kc + t4 + 4];
            asm("mma.sync.aligned.m16n8k8.row.col.f32.tf32.tf32.f32 "
                "{%0,%1,%2,%3}, {%4,%5,%6,%7}, {%8,%9}, {%0,%1,%2,%3};"
                : "+f"(acc[0]), "+f"(acc[1]), "+f"(acc[2]), "+f"(acc[3])
                : "r"(a0), "r"(a1), "r"(a2), "r"(a3), "r"(b0), "r"(b1));
        }
        __syncthreads();
    }

    // GEMM partials (slot 2z+wg)
    float* part = g_part + (size_t)(2 * z + wg) * B_ * C_;
    int orow = bm0 + wm + g;
    int col = wn + 2 * t4;
    *(float2*)&part[orow * C_ + col]       = make_float2(acc[0], acc[1]);
    *(float2*)&part[(orow + 8) * C_ + col] = make_float2(acc[2], acc[3]);

    // S1u partials: warp wd staged row wd -> full-warp reduce, lane0 writes
    {
        float v = s1a;
        #pragma unroll
        for (int o = 16; o; o >>= 1) v += __shfl_xor_sync(0xffffffffu, v, o);
        if (lane == 0) g_S1part[z * B_ + bm0 + srow] = v;
    }

    // last-z-block-done loss epilogue (atomicInc wraps -> replay-safe)
    __threadfence();
    __syncthreads();
    if (tid == 0) {
        unsigned old = atomicInc(&g_cnt[blockIdx.x], ZSPLIT - 1);
        s_last = (old == ZSPLIT - 1);
    }
    __syncthreads();
    if (s_last) {
        float inv = 1.f / (__ldg(&g_spsum[0]) + __ldg(&g_spsum[1]) +
                           __ldg(&g_spsum[2]) + __ldg(&g_spsum[3]));
        for (int o = tid; o < MBLK * C_; o += NTHR) {
            int b = bm0 + (o >> 6), c = o & 63;
            float s = 0.f, s1 = 0.f;
            #pragma unroll
            for (int zz = 0; zz < 2 * ZSPLIT; zz++)
                s += __ldcg(&g_part[(size_t)zz * B_ * C_ + b * C_ + c]);
            #pragma unroll
            for (int zz = 0; zz < ZSPLIT; zz++)
                s1 += __ldcg(&g_S1part[zz * B_ + b]);
            out[O_LOSS + b * C_ + c] = inv * (s1 - 2.f * s);
        }
    }
}

// ---------------------------------------------------------------------------
extern "C" void kernel_launch(void* const* d_in, const int* in_sizes, int n_in,
                              void* d_out, int out_size) {
    const float* input_seq  = (const float*)d_in[0];
    const int*   label      = (const int*)  d_in[1];
    const float* mask       = (const float*)d_in[2];
    const float* prototypes = (const float*)d_in[3];
    const float* weights    = (const float*)d_in[4];
    const float* protocount = (const float*)d_in[5];
    float* out = (float*)d_out;

    prep_kernel<<<C_ + B_ + 1, 256>>>(input_seq, label, mask, prototypes,
                                      weights, protocount, out);
    cudaFuncSetAttribute(gemm_kernel,
                         cudaFuncAttributeMaxDynamicSharedMemorySize, GEMM_SMEM);
    gemm_kernel<<<dim3(8, ZSPLIT), NTHR, GEMM_SMEM>>>(input_seq, mask,
                                                      weights, out);
}